// round 8
// baseline (speedup 1.0000x reference)
#include <cuda_runtime.h>
#include <cuda_bf16.h>
#include <cstdint>

// Problem constants
#define N_SAMPLES    65536
#define START_SIZE   4096
#define N_EVENTS     32
#define ROW_F4       (N_SAMPLES / 4)          // 16384 float4 per row
#define SEGS_PER_ROW 8
#define SEG_F4       (ROW_F4 / SEGS_PER_ROW)  // 2048 float4 per segment
#define THREADS      256
#define F4_PER_THR   (SEG_F4 / THREADS)       // 8
#define POS_F4       (START_SIZE / 4)         // 1024 float4 per event
#define POS_ITERS    (POS_F4 / THREADS)       // 4
#define NWARPS       (THREADS / 32)           // 8
#define CHUNK        4                        // float4 held live per copy wave

__global__ void __launch_bounds__(THREADS)
fused_shift_kernel(const float4* __restrict__ in,
                   const float4* __restrict__ pos,
                   float4* __restrict__ out)
{
    const int bid = blockIdx.x;
    const int tid = threadIdx.x;
    const int row = bid >> 3;                   // bid / SEGS_PER_ROW
    const int seg = bid & (SEGS_PER_ROW - 1);
    const int e   = row & (N_EVENTS - 1);
    const size_t rbase = (size_t)row * ROW_F4;
    const int j0 = seg * SEG_F4 + tid;
    const float4* src_base = in + rbase + j0;

    // ---- Phase 0: L2 prefetch of the whole segment (no registers) --------
    #pragma unroll
    for (int k = 0; k < F4_PER_THR; k++)
        asm volatile("prefetch.global.L2 [%0];" :: "l"(src_base + k * THREADS));

    // ---- Phase 1: single-pass argmax over pos[e] --------------------------
    // jnp.argmax tie rule (first index wins): ascending order, strict '>'.
    const float4* p4 = pos + (size_t)e * POS_F4;
    float    bv = __int_as_float(0xff800000);   // -inf
    unsigned bi = 0u;
    #pragma unroll
    for (int kk = 0; kk < POS_ITERS; kk++) {
        const int i4 = tid + kk * THREADS;
        const float4 v = p4[i4];
        const unsigned b = (unsigned)(i4 * 4);
        if (v.x > bv) { bv = v.x; bi = b + 0u; }
        if (v.y > bv) { bv = v.y; bi = b + 1u; }
        if (v.z > bv) { bv = v.z; bi = b + 2u; }
        if (v.w > bv) { bv = v.w; bi = b + 3u; }
    }
    // warp reduce (val, idx): larger value wins; equal value -> smaller idx
    #pragma unroll
    for (int off = 16; off > 0; off >>= 1) {
        const float    ov = __shfl_down_sync(0xFFFFFFFFu, bv, off);
        const unsigned oi = __shfl_down_sync(0xFFFFFFFFu, bi, off);
        if (ov > bv || (ov == bv && oi < bi)) { bv = ov; bi = oi; }
    }

    __shared__ float    s_v[NWARPS];
    __shared__ unsigned s_i[NWARPS];
    __shared__ int s_d4;
    if ((tid & 31) == 0) { s_v[tid >> 5] = bv; s_i[tid >> 5] = bi; }
    __syncthreads();
    if (tid == 0) {
        float    cv = s_v[0];
        unsigned ci = s_i[0];
        #pragma unroll
        for (int w = 1; w < NWARPS; w++) {
            const float ov = s_v[w];
            const unsigned oi = s_i[w];
            if (ov > cv || (ov == cv && oi < ci)) { cv = ov; ci = oi; }
        }
        s_d4 = (int)ci * 4;                   // STEP=16 floats = 4 float4
    }
    __syncthreads();
    const int d4 = s_d4;

    // ---- Phase 2: shifted copy in CHUNK-wide waves (bounded registers) ----
    // out[(j+d4) mod ROW_F4]: jp < ROW_F4 -> in[j], else 0 (head zeroing).
    float4* dst_base = out + rbase;
    const float4 zero = make_float4(0.f, 0.f, 0.f, 0.f);
    #pragma unroll 1
    for (int c = 0; c < F4_PER_THR / CHUNK; c++) {
        float4 v[CHUNK];
        #pragma unroll
        for (int k = 0; k < CHUNK; k++)
            v[k] = src_base[(c * CHUNK + k) * THREADS];
        #pragma unroll
        for (int k = 0; k < CHUNK; k++) {
            const int jp = j0 + (c * CHUNK + k) * THREADS + d4;
            if (jp < ROW_F4) {
                __stcs(dst_base + jp, v[k]);
            } else {
                __stcs(dst_base + jp - ROW_F4, zero);
            }
        }
    }
}

extern "C" void kernel_launch(void* const* d_in, const int* in_sizes, int n_in,
                              void* d_out, int out_size) {
    const float* events = (const float*)d_in[0];   // (B, 32, 65536) f32
    const float* pos    = (const float*)d_in[1];   // (1, 32, 4096)  f32

    const int batch = in_sizes[0] / (N_EVENTS * N_SAMPLES);   // 8
    const int rows  = batch * N_EVENTS;                       // 256
    const int grid  = rows * SEGS_PER_ROW;                    // 2048

    fused_shift_kernel<<<grid, THREADS>>>((const float4*)events,
                                          (const float4*)pos,
                                          (float4*)d_out);
}

// round 9
// speedup vs baseline: 1.0014x; 1.0014x over previous
#include <cuda_runtime.h>
#include <cuda_bf16.h>
#include <cstdint>

// Problem constants
#define N_SAMPLES    65536
#define START_SIZE   4096
#define N_EVENTS     32
#define ROW_F4       (N_SAMPLES / 4)          // 16384 float4 per row
#define SEGS_PER_ROW 4
#define SEG_F4       (ROW_F4 / SEGS_PER_ROW)  // 4096 float4 per segment
#define THREADS      512
#define F4_PER_THR   (SEG_F4 / THREADS)       // 8
#define POS_F4       (START_SIZE / 4)         // 1024 float4 per event
#define POS_ITERS    (POS_F4 / THREADS)       // 2
#define NWARPS       (THREADS / 32)           // 16
#define CHUNK        4                        // float4 held live per copy wave

__global__ void __launch_bounds__(THREADS)
fused_shift_kernel(const float4* __restrict__ in,
                   const float4* __restrict__ pos,
                   float4* __restrict__ out)
{
    const int bid = blockIdx.x;
    const int tid = threadIdx.x;
    const int row = bid >> 2;                   // bid / SEGS_PER_ROW
    const int seg = bid & (SEGS_PER_ROW - 1);
    const int e   = row & (N_EVENTS - 1);
    const size_t rbase = (size_t)row * ROW_F4;
    const int j0 = seg * SEG_F4 + tid;
    const float4* src_base = in + rbase + j0;

    // ---- Phase 0a: pos loads FIRST (argmax critical path heads the
    //      per-SM L1tex queue; everything else lines up behind it) ---------
    const float4* p4 = pos + (size_t)e * POS_F4;
    float4 pv[POS_ITERS];
    #pragma unroll
    for (int kk = 0; kk < POS_ITERS; kk++)
        pv[kk] = p4[tid + kk * THREADS];

    // ---- Phase 0b: register-free L2 prefetch of the event segment --------
    #pragma unroll
    for (int k = 0; k < F4_PER_THR; k++)
        asm volatile("prefetch.global.L2 [%0];" :: "l"(src_base + k * THREADS));

    // ---- Phase 1: single-pass argmax (jnp first-index tie rule) ----------
    float    bv = __int_as_float(0xff800000);   // -inf
    unsigned bi = 0u;
    #pragma unroll
    for (int kk = 0; kk < POS_ITERS; kk++) {
        const unsigned b = (unsigned)((tid + kk * THREADS) * 4);
        const float4 v = pv[kk];
        if (v.x > bv) { bv = v.x; bi = b + 0u; }
        if (v.y > bv) { bv = v.y; bi = b + 1u; }
        if (v.z > bv) { bv = v.z; bi = b + 2u; }
        if (v.w > bv) { bv = v.w; bi = b + 3u; }
    }
    // warp reduce (val, idx): larger value wins; equal value -> smaller idx
    #pragma unroll
    for (int off = 16; off > 0; off >>= 1) {
        const float    ov = __shfl_down_sync(0xFFFFFFFFu, bv, off);
        const unsigned oi = __shfl_down_sync(0xFFFFFFFFu, bi, off);
        if (ov > bv || (ov == bv && oi < bi)) { bv = ov; bi = oi; }
    }

    __shared__ float    s_v[NWARPS];
    __shared__ unsigned s_i[NWARPS];
    __shared__ int s_d4;
    if ((tid & 31) == 0) { s_v[tid >> 5] = bv; s_i[tid >> 5] = bi; }
    __syncthreads();
    if (tid == 0) {
        float    cv = s_v[0];
        unsigned ci = s_i[0];
        #pragma unroll
        for (int w = 1; w < NWARPS; w++) {
            const float ov = s_v[w];
            const unsigned oi = s_i[w];
            if (ov > cv || (ov == cv && oi < ci)) { cv = ov; ci = oi; }
        }
        s_d4 = (int)ci * 4;                   // STEP=16 floats = 4 float4
    }
    __syncthreads();
    const int d4 = s_d4;

    // ---- Phase 2: shifted copy in CHUNK-wide waves (bounded registers) ----
    // out[(j+d4) mod ROW_F4]: jp < ROW_F4 -> in[j], else 0 (head zeroing).
    float4* dst_base = out + rbase;
    const float4 zero = make_float4(0.f, 0.f, 0.f, 0.f);
    #pragma unroll 1
    for (int c = 0; c < F4_PER_THR / CHUNK; c++) {
        float4 v[CHUNK];
        #pragma unroll
        for (int k = 0; k < CHUNK; k++)
            v[k] = src_base[(c * CHUNK + k) * THREADS];
        #pragma unroll
        for (int k = 0; k < CHUNK; k++) {
            const int jp = j0 + (c * CHUNK + k) * THREADS + d4;
            if (jp < ROW_F4) {
                __stcs(dst_base + jp, v[k]);
            } else {
                __stcs(dst_base + jp - ROW_F4, zero);
            }
        }
    }
}

extern "C" void kernel_launch(void* const* d_in, const int* in_sizes, int n_in,
                              void* d_out, int out_size) {
    const float* events = (const float*)d_in[0];   // (B, 32, 65536) f32
    const float* pos    = (const float*)d_in[1];   // (1, 32, 4096)  f32

    const int batch = in_sizes[0] / (N_EVENTS * N_SAMPLES);   // 8
    const int rows  = batch * N_EVENTS;                       // 256
    const int grid  = rows * SEGS_PER_ROW;                    // 1024

    fused_shift_kernel<<<grid, THREADS>>>((const float4*)events,
                                          (const float4*)pos,
                                          (float4*)d_out);
}